// round 15
// baseline (speedup 1.0000x reference)
#include <cuda_runtime.h>
#include <cuda_fp16.h>
#include <cstdint>

#define BB 2
#define TT 2048
#define CC 1024
#define HH 16
#define DD 64
#define C3 3072
#define MROWS 4096   // BB*TT
#define NBH 32       // BB*HH

// ---------------- device global scratch ----------------
__device__ __align__(16) __half g_x[MROWS * CC];     // x fp16
__device__ __align__(16) __half g_wa[C3 * CC];       // w_attn^T fp16 (q cols pre-scaled)
__device__ __align__(16) __half g_wp[CC * CC];       // w_proj^T fp16
__device__ __align__(16) __half g_q[MROWS * CC];     // q fp16 [b,t,h*d]
__device__ __align__(16) __half g_k[MROWS * CC];     // k fp16
__device__ __align__(16) __half g_v[MROWS * CC];     // v fp16
__device__ __align__(16) __half g_y[MROWS * CC];     // attn out fp16

// ---------------- helpers ----------------
__device__ __forceinline__ uint32_t smem_u32(const void* p) {
    uint32_t a;
    asm("{ .reg .u64 t; cvta.to.shared.u64 t, %1; cvt.u32.u64 %0, t; }" : "=r"(a) : "l"(p));
    return a;
}
__device__ __forceinline__ void cp16(uint32_t s, const void* g) {
    asm volatile("cp.async.cg.shared.global [%0], [%1], 16;" :: "r"(s), "l"(g));
}
__device__ __forceinline__ void ldm_x4(uint32_t addr, uint32_t* r) {
    asm volatile("ldmatrix.sync.aligned.m8n8.x4.shared.b16 {%0,%1,%2,%3}, [%4];"
                 : "=r"(r[0]), "=r"(r[1]), "=r"(r[2]), "=r"(r[3]) : "r"(addr));
}
__device__ __forceinline__ void ldm_x4t(uint32_t addr, uint32_t* r) {
    asm volatile("ldmatrix.sync.aligned.m8n8.x4.trans.shared.b16 {%0,%1,%2,%3}, [%4];"
                 : "=r"(r[0]), "=r"(r[1]), "=r"(r[2]), "=r"(r[3]) : "r"(addr));
}
__device__ __forceinline__ void mma16816(float* c, const uint32_t* a, const uint32_t* b) {
    asm volatile("mma.sync.aligned.m16n8k16.row.col.f32.f16.f16.f32 "
                 "{%0,%1,%2,%3}, {%4,%5,%6,%7}, {%8,%9}, {%0,%1,%2,%3};"
                 : "+f"(c[0]), "+f"(c[1]), "+f"(c[2]), "+f"(c[3])
                 : "r"(a[0]), "r"(a[1]), "r"(a[2]), "r"(a[3]), "r"(b[0]), "r"(b[1]));
}
__device__ __forceinline__ uint32_t pack2h(float x, float y) {
    __half2 h = __floats2half2_rn(x, y);
    return *(uint32_t*)&h;
}
__device__ __forceinline__ float ex2(float x) {
    float y;
    asm("ex2.approx.ftz.f32 %0, %1;" : "=f"(y) : "f"(x));
    return y;
}

// ---------------- merged prep kernel ----------------
__global__ void __launch_bounds__(256) prep_k(const float* __restrict__ x,
                                              const float* __restrict__ wa,
                                              const float* __restrict__ wp) {
    __shared__ float ts[32][33];
    const int id = blockIdx.x;
    const int tid = threadIdx.x;
    if (id < 4096) {
        size_t i = ((size_t)id * 256 + tid) * 4;
        float4 v = *(const float4*)(x + i);
        __half h[4] = {__float2half_rn(v.x), __float2half_rn(v.y),
                       __float2half_rn(v.z), __float2half_rn(v.w)};
        *(uint2*)(g_x + i) = *(uint2*)h;
        return;
    }
    const int isattn = (id < 7168);
    const int j = isattn ? (id - 4096) : (id - 7168);
    const int NBLK = isattn ? 96 : 32;
    const int N = isattn ? C3 : CC;
    const float* w = isattn ? wa : wp;
    __half* t = isattn ? g_wa : g_wp;
    const int n0 = (j % NBLK) * 32, c0 = (j / NBLK) * 32;
    const int tx = tid & 31, ty = tid >> 5;
#pragma unroll
    for (int jj = 0; jj < 4; jj++)
        ts[ty + jj * 8][tx] = w[(size_t)(c0 + ty + jj * 8) * N + n0 + tx];
    __syncthreads();
#pragma unroll
    for (int jj = 0; jj < 4; jj++) {
        int n = n0 + ty + jj * 8;
        float v = ts[tx][ty + jj * 8];
        if (isattn && n < CC) v *= 0.18033688011112042f;  // (1/sqrt 64)*log2(e)
        t[(size_t)n * CC + c0 + tx] = __float2half_rn(v);
    }
}

// ---------------- mma.sync GEMM (CTA 128x128, 2 CTA/SM, 4-stage pipeline) ----------------
template<int MODE>
__global__ void __launch_bounds__(256, 2) gemm_mma(float* __restrict__ outp, int moff) {
    constexpr int NTILE = 128;
    constexpr int NC  = 32;
    constexpr int LDA = CC, LDB = CC;
    constexpr int WN  = NTILE / 2;
    constexpr int NN8 = WN / 8;
    constexpr int NJ  = WN / 16;
    constexpr int ASZ = 128 * 80;
    constexpr int STG = 2 * ASZ;
    constexpr int NSTG = 4;

    extern __shared__ char sm[];
    const uint32_t smu = smem_u32(sm);
    const int tid = threadIdx.x, lane = tid & 31, wid = tid >> 5;
    const int wm = wid & 3, wn = wid >> 2;
    const int warpM = wm * 32, warpN = wn * WN;
    const int nt = blockIdx.x, mt = blockIdx.y + moff;
    const int m0 = mt * 128, n0 = nt * NTILE;

    const __half *a_p, *b_p;
    if constexpr (MODE == 0) {
        a_p = g_x + (size_t)m0 * CC;
        b_p = g_wa + (size_t)n0 * CC;
    } else {
        a_p = g_y + (size_t)m0 * CC;
        b_p = g_wp + (size_t)n0 * CC;
    }

    auto load_stage = [&](int st, int kc) {
        const uint32_t s0 = smu + st * STG;
        const int k0 = kc * 32;
#pragma unroll
        for (int i0 = 0; i0 < 128 * 4; i0 += 256) {
            int i = i0 + tid, r = i >> 2, c = i & 3;
            uint32_t sa = s0 + r * 80 + c * 16;
            cp16(sa,       (const char*)(a_p + (size_t)r * LDA + k0) + c * 16);
            cp16(sa + ASZ, (const char*)(b_p + (size_t)r * LDB + k0) + c * 16);
        }
        asm volatile("cp.async.commit_group;" ::: "memory");
    };

    const int grp = lane >> 3, r8 = lane & 7;
    const uint32_t aOff = (uint32_t)((warpM + r8 + (grp & 1) * 8) * 80 + (grp >> 1) * 16);
    const uint32_t bOff = (uint32_t)((warpN + r8 + (grp >> 1) * 8) * 80 + (grp & 1) * 16);

    float acc[2][NN8][4];
#pragma unroll
    for (int mi = 0; mi < 2; mi++)
#pragma unroll
        for (int ni = 0; ni < NN8; ni++)
#pragma unroll
            for (int e = 0; e < 4; e++) acc[mi][ni][e] = 0.f;

    load_stage(0, 0);
    load_stage(1, 1);
    load_stage(2, 2);

    int st = 0;
    for (int c = 0; c < NC; c++) {
        if (c + 3 < NC)      { asm volatile("cp.async.wait_group 2;" ::: "memory"); }
        else if (c + 2 < NC) { asm volatile("cp.async.wait_group 2;" ::: "memory"); }
        else if (c + 1 < NC) { asm volatile("cp.async.wait_group 1;" ::: "memory"); }
        else                 { asm volatile("cp.async.wait_group 0;" ::: "memory"); }
        __syncthreads();
        if (c + 3 < NC) {
            int st2 = st + 3; if (st2 >= NSTG) st2 -= NSTG;
            load_stage(st2, c + 3);
        }

        const uint32_t sA = smu + st * STG;
        const uint32_t sB = sA + ASZ;
        uint32_t aF[2][2][4], bF[2][NJ][4];
#pragma unroll
        for (int kk = 0; kk < 2; kk++) {
            const uint32_t kb = kk * 32;
            ldm_x4(sA + aOff + kb,           aF[kk][0]);
            ldm_x4(sA + aOff + 16 * 80 + kb, aF[kk][1]);
#pragma unroll
            for (int nj = 0; nj < NJ; nj++)
                ldm_x4(sB + bOff + nj * 16 * 80 + kb, bF[kk][nj]);
        }
#pragma unroll
        for (int kk = 0; kk < 2; kk++)
#pragma unroll
            for (int mi = 0; mi < 2; mi++)
#pragma unroll
                for (int ni = 0; ni < NN8; ni++)
                    mma16816(acc[mi][ni], aF[kk][mi], &bF[kk][ni >> 1][(ni & 1) * 2]);
        if (++st == NSTG) st = 0;
    }

    const int row_l = lane >> 2, col_l = (lane & 3) * 2;
#pragma unroll
    for (int mi = 0; mi < 2; mi++) {
#pragma unroll
        for (int ni = 0; ni < NN8; ni++) {
            const int gr0 = m0 + warpM + mi * 16 + row_l;
            const int gc  = n0 + warpN + ni * 8 + col_l;
            const float* cc = acc[mi][ni];
            if constexpr (MODE == 0) {
                __half* dst;
                int gcl;
                if (gc < CC)           { dst = g_q; gcl = gc; }
                else if (gc < 2 * CC)  { dst = g_k; gcl = gc - CC; }
                else                   { dst = g_v; gcl = gc - 2 * CC; }
                *(uint32_t*)(dst + (size_t)gr0 * CC + gcl)       = pack2h(cc[0], cc[1]);
                *(uint32_t*)(dst + (size_t)(gr0 + 8) * CC + gcl) = pack2h(cc[2], cc[3]);
            } else {
                *(float2*)(outp + (size_t)gr0 * CC + gc)       = make_float2(cc[0], cc[1]);
                *(float2*)(outp + (size_t)(gr0 + 8) * CC + gc) = make_float2(cc[2], cc[3]);
            }
        }
    }
}

// ---------------- fused flash attention: 4 warps x 32 q-rows, 4-stage pipeline ----------------
__global__ void __launch_bounds__(128) flash_k(int bhoff) {
    constexpr int RSTR = 144;
    constexpr int BUF  = 64 * RSTR;
    constexpr int STG  = 2 * BUF;
    constexpr int NSTG = 4;
    constexpr int NT   = TT / 64;

    extern __shared__ char sm[];
    const uint32_t smu = smem_u32(sm);
    const int tid = threadIdx.x, lane = tid & 31, wid = tid >> 5;
    const int qt = blockIdx.x, bh = blockIdx.y + bhoff;
    const int b = bh >> 4, h = bh & 15;
    const int r = lane >> 2, cq = (lane & 3) * 2;

    const size_t qbase = ((size_t)b * TT + qt * 128 + wid * 32) * CC + h * DD;
    uint32_t qf[2][4][4];
#pragma unroll
    for (int mb = 0; mb < 2; mb++)
#pragma unroll
        for (int kc = 0; kc < 4; kc++)
#pragma unroll
            for (int e = 0; e < 4; e++) {
                size_t off = qbase + (size_t)(mb * 16 + r + (e & 1) * 8) * CC
                           + kc * 16 + cq + (e >> 1) * 8;
                qf[mb][kc][e] = *(const uint32_t*)(g_q + off);
            }

    float oacc[2][8][4];
#pragma unroll
    for (int mb = 0; mb < 2; mb++)
#pragma unroll
        for (int nf = 0; nf < 8; nf++)
#pragma unroll
            for (int e = 0; e < 4; e++) oacc[mb][nf][e] = 0.f;
    float mrow[2][2] = {{-1e30f, -1e30f}, {-1e30f, -1e30f}};
    float lrow[2][2] = {{0.f, 0.f}, {0.f, 0.f}};

    const int grp = lane >> 3, r8 = lane & 7;
    const uint32_t kOff = (uint32_t)((r8 + (grp >> 1) * 8) * RSTR + (grp & 1) * 16);
    const uint32_t vOff = (uint32_t)(((grp & 1) * 8 + r8) * RSTR + (grp >> 1) * 16);
    const size_t kvb = (size_t)b * TT * CC + h * DD;

    auto load_tile = [&](int kt, int st) {
        const uint32_t s0 = smu + st * STG;
        const int t0 = kt * 64;
#pragma unroll
        for (int it = 0; it < 4; it++) {
            int i = it * 128 + tid;
            int rr = i >> 3, c = i & 7;
            uint32_t sa = s0 + rr * RSTR + c * 16;
            cp16(sa,       (const char*)(g_k + kvb + (size_t)(t0 + rr) * CC) + c * 16);
            cp16(sa + BUF, (const char*)(g_v + kvb + (size_t)(t0 + rr) * CC) + c * 16);
        }
        asm volatile("cp.async.commit_group;" ::: "memory");
    };

    load_tile(0, 0);
    load_tile(1, 1);
    load_tile(2, 2);

    int st = 0;
    for (int kt = 0; kt < NT; kt++) {
        if (kt + 2 < NT)      { asm volatile("cp.async.wait_group 2;" ::: "memory"); }
        else if (kt + 1 < NT) { asm volatile("cp.async.wait_group 1;" ::: "memory"); }
        else                  { asm volatile("cp.async.wait_group 0;" ::: "memory"); }
        __syncthreads();
        if (kt + 3 < NT) {
            int st2 = st + 3; if (st2 >= NSTG) st2 -= NSTG;
            load_tile(kt + 3, st2);
        }

        const uint32_t sK = smu + st * STG;
        const uint32_t sV = sK + BUF;

        // ---- S = Q K^T: each bF feeds both m-blocks ----
        float sacc[2][8][4];
#pragma unroll
        for (int mb = 0; mb < 2; mb++)
#pragma unroll
            for (int nf = 0; nf < 8; nf++)
#pragma unroll
                for (int e = 0; e < 4; e++) sacc[mb][nf][e] = 0.f;
#pragma unroll
        for (int kk = 0; kk < 4; kk++) {
            uint32_t bF[4][4];
#pragma unroll
            for (int nj = 0; nj < 4; nj++)
                ldm_x4(sK + kOff + nj * 16 * RSTR + kk * 32, bF[nj]);
#pragma unroll
            for (int mb = 0; mb < 2; mb++)
#pragma unroll
                for (int nf = 0; nf < 8; nf++)
                    mma16816(sacc[mb][nf], qf[mb][kk], &bF[nf >> 1][(nf & 1) * 2]);
        }

        // ---- online softmax (exp2 domain) per m-block ----
#pragma unroll
        for (int mb = 0; mb < 2; mb++) {
            float mx0 = -1e30f, mx1 = -1e30f;
#pragma unroll
            for (int nf = 0; nf < 8; nf++) {
                mx0 = fmaxf(mx0, fmaxf(sacc[mb][nf][0], sacc[mb][nf][1]));
                mx1 = fmaxf(mx1, fmaxf(sacc[mb][nf][2], sacc[mb][nf][3]));
            }
            mx0 = fmaxf(mx0, __shfl_xor_sync(0xffffffffu, mx0, 1));
            mx0 = fmaxf(mx0, __shfl_xor_sync(0xffffffffu, mx0, 2));
            mx1 = fmaxf(mx1, __shfl_xor_sync(0xffffffffu, mx1, 1));
            mx1 = fmaxf(mx1, __shfl_xor_sync(0xffffffffu, mx1, 2));
            const float mn0 = fmaxf(mrow[mb][0], mx0), mn1 = fmaxf(mrow[mb][1], mx1);
            const float al0 = ex2(mrow[mb][0] - mn0), al1 = ex2(mrow[mb][1] - mn1);
            float ls0 = 0.f, ls1 = 0.f;
#pragma unroll
            for (int nf = 0; nf < 8; nf++) {
                sacc[mb][nf][0] = ex2(sacc[mb][nf][0] - mn0);
                sacc[mb][nf][1] = ex2(sacc[mb][nf][1] - mn0);
                sacc[mb][nf][2] = ex2(sacc[mb][nf][2] - mn1);
                sacc[mb][nf][3] = ex2(sacc[mb][nf][3] - mn1);
                ls0 += sacc[mb][nf][0] + sacc[mb][nf][1];
                ls1 += sacc[mb][nf][2] + sacc[mb][nf][3];
            }
            ls0 += __shfl_xor_sync(0xffffffffu, ls0, 1);
            ls0 += __shfl_xor_sync(0xffffffffu, ls0, 2);
            ls1 += __shfl_xor_sync(0xffffffffu, ls1, 1);
            ls1 += __shfl_xor_sync(0xffffffffu, ls1, 2);
            lrow[mb][0] = lrow[mb][0] * al0 + ls0; mrow[mb][0] = mn0;
            lrow[mb][1] = lrow[mb][1] * al1 + ls1; mrow[mb][1] = mn1;
#pragma unroll
            for (int nf = 0; nf < 8; nf++) {
                oacc[mb][nf][0] *= al0; oacc[mb][nf][1] *= al0;
                oacc[mb][nf][2] *= al1; oacc[mb][nf][3] *= al1;
            }
        }

        // ---- P -> fp16 A-fragments ----
        uint32_t pf[2][4][4];
#pragma unroll
        for (int mb = 0; mb < 2; mb++)
#pragma unroll
            for (int kc = 0; kc < 4; kc++) {
                pf[mb][kc][0] = pack2h(sacc[mb][2 * kc][0],     sacc[mb][2 * kc][1]);
                pf[mb][kc][1] = pack2h(sacc[mb][2 * kc][2],     sacc[mb][2 * kc][3]);
                pf[mb][kc][2] = pack2h(sacc[mb][2 * kc + 1][0], sacc[mb][2 * kc + 1][1]);
                pf[mb][kc][3] = pack2h(sacc[mb][2 * kc + 1][2], sacc[mb][2 * kc + 1][3]);
            }

        // ---- O += P V: each vF feeds both m-blocks ----
#pragma unroll
        for (int kc = 0; kc < 4; kc++) {
            uint32_t vF[4][4];
#pragma unroll
            for (int db = 0; db < 4; db++)
                ldm_x4t(sV + kc * 16 * RSTR + vOff + db * 32, vF[db]);
#pragma unroll
            for (int mb = 0; mb < 2; mb++)
#pragma unroll
                for (int nf = 0; nf < 8; nf++)
                    mma16816(oacc[mb][nf], pf[mb][kc], &vF[nf >> 1][(nf & 1) * 2]);
        }
        if (++st == NSTG) st = 0;
    }

    // ---- epilogue ----
#pragma unroll
    for (int mb = 0; mb < 2; mb++) {
        const float inv0 = 1.f / lrow[mb][0], inv1 = 1.f / lrow[mb][1];
        const size_t yb = ((size_t)b * TT + qt * 128 + wid * 32 + mb * 16) * CC + h * DD;
#pragma unroll
        for (int nf = 0; nf < 8; nf++) {
            const int col = nf * 8 + cq;
            *(uint32_t*)(g_y + yb + (size_t)r * CC + col) =
                pack2h(oacc[mb][nf][0] * inv0, oacc[mb][nf][1] * inv0);
            *(uint32_t*)(g_y + yb + (size_t)(r + 8) * CC + col) =
                pack2h(oacc[mb][nf][2] * inv1, oacc[mb][nf][3] * inv1);
        }
    }
}

// ---------------- host launcher: per-batch chains on forked streams ----------------
extern "C" void kernel_launch(void* const* d_in, const int* in_sizes, int n_in,
                              void* d_out, int out_size) {
    const float* x  = (const float*)d_in[0];
    const float* wa = (const float*)d_in[1];
    const float* wp = (const float*)d_in[2];
    float* out = (float*)d_out;

    constexpr int SM_GEMM  = 4 * 2 * 128 * 80;   // 81920
    constexpr int SM_FLASH = 4 * 2 * 64 * 144;   // 73728

    static cudaStream_t s2 = nullptr;
    static cudaEvent_t e_fork = nullptr, e_join = nullptr;
    if (!s2) {
        cudaStreamCreateWithFlags(&s2, cudaStreamNonBlocking);
        cudaEventCreateWithFlags(&e_fork, cudaEventDisableTiming);
        cudaEventCreateWithFlags(&e_join, cudaEventDisableTiming);
        cudaFuncSetAttribute((const void*)gemm_mma<0>, cudaFuncAttributeMaxDynamicSharedMemorySize, SM_GEMM);
        cudaFuncSetAttribute((const void*)gemm_mma<1>, cudaFuncAttributeMaxDynamicSharedMemorySize, SM_GEMM);
        cudaFuncSetAttribute((const void*)flash_k,     cudaFuncAttributeMaxDynamicSharedMemorySize, SM_FLASH);
    }

    prep_k<<<8192, 256>>>(x, wa, wp);

    cudaEventRecord(e_fork, 0);
    cudaStreamWaitEvent(s2, e_fork, 0);

    // batch 0 chain (default stream)
    gemm_mma<0><<<dim3(C3 / 128, 16), 256, SM_GEMM>>>(nullptr, 0);
    flash_k<<<dim3(TT / 128, 16), 128, SM_FLASH>>>(0);
    gemm_mma<1><<<dim3(CC / 128, 16), 256, SM_GEMM>>>(out, 0);

    // batch 1 chain (s2)
    gemm_mma<0><<<dim3(C3 / 128, 16), 256, SM_GEMM, s2>>>(nullptr, 16);
    flash_k<<<dim3(TT / 128, 16), 128, SM_FLASH, s2>>>(16);
    gemm_mma<1><<<dim3(CC / 128, 16), 256, SM_GEMM, s2>>>(out, 16);

    cudaEventRecord(e_join, s2);
    cudaStreamWaitEvent(0, e_join, 0);
}

// round 17
// speedup vs baseline: 1.0545x; 1.0545x over previous
#include <cuda_runtime.h>
#include <cuda_fp16.h>
#include <cstdint>

#define BB 2
#define TT 2048
#define CC 1024
#define HH 16
#define DD 64
#define C3 3072
#define MROWS 4096   // BB*TT
#define NBH 32       // BB*HH

// ---------------- device global scratch ----------------
__device__ __align__(16) __half g_x[MROWS * CC];     // x fp16
__device__ __align__(16) __half g_wa[C3 * CC];       // w_attn^T fp16 (q cols pre-scaled)
__device__ __align__(16) __half g_wp[CC * CC];       // w_proj^T fp16
__device__ __align__(16) __half g_q[MROWS * CC];     // q fp16 [b,t,h*d]
__device__ __align__(16) __half g_k[MROWS * CC];     // k fp16
__device__ __align__(16) __half g_v[MROWS * CC];     // v fp16
__device__ __align__(16) __half g_y[MROWS * CC];     // attn out fp16

// ---------------- helpers ----------------
__device__ __forceinline__ uint32_t smem_u32(const void* p) {
    uint32_t a;
    asm("{ .reg .u64 t; cvta.to.shared.u64 t, %1; cvt.u32.u64 %0, t; }" : "=r"(a) : "l"(p));
    return a;
}
__device__ __forceinline__ void cp16(uint32_t s, const void* g) {
    asm volatile("cp.async.cg.shared.global [%0], [%1], 16;" :: "r"(s), "l"(g));
}
__device__ __forceinline__ void ldm_x4(uint32_t addr, uint32_t* r) {
    asm volatile("ldmatrix.sync.aligned.m8n8.x4.shared.b16 {%0,%1,%2,%3}, [%4];"
                 : "=r"(r[0]), "=r"(r[1]), "=r"(r[2]), "=r"(r[3]) : "r"(addr));
}
__device__ __forceinline__ void ldm_x4t(uint32_t addr, uint32_t* r) {
    asm volatile("ldmatrix.sync.aligned.m8n8.x4.trans.shared.b16 {%0,%1,%2,%3}, [%4];"
                 : "=r"(r[0]), "=r"(r[1]), "=r"(r[2]), "=r"(r[3]) : "r"(addr));
}
__device__ __forceinline__ void mma16816(float* c, const uint32_t* a, const uint32_t* b) {
    asm volatile("mma.sync.aligned.m16n8k16.row.col.f32.f16.f16.f32 "
                 "{%0,%1,%2,%3}, {%4,%5,%6,%7}, {%8,%9}, {%0,%1,%2,%3};"
                 : "+f"(c[0]), "+f"(c[1]), "+f"(c[2]), "+f"(c[3])
                 : "r"(a[0]), "r"(a[1]), "r"(a[2]), "r"(a[3]), "r"(b[0]), "r"(b[1]));
}
__device__ __forceinline__ uint32_t pack2h(float x, float y) {
    __half2 h = __floats2half2_rn(x, y);
    return *(uint32_t*)&h;
}
__device__ __forceinline__ float ex2(float x) {
    float y;
    asm("ex2.approx.ftz.f32 %0, %1;" : "=f"(y) : "f"(x));
    return y;
}

// ---------------- prep kernels ----------------
// prep_xwa: blocks [0,4096) x convert; [4096,7168) w_attn transpose
__global__ void __launch_bounds__(256) prep_xwa(const float* __restrict__ x,
                                                const float* __restrict__ wa) {
    __shared__ float ts[32][33];
    const int id = blockIdx.x;
    const int tid = threadIdx.x;
    if (id < 4096) {
        size_t i = ((size_t)id * 256 + tid) * 4;
        float4 v = *(const float4*)(x + i);
        __half h[4] = {__float2half_rn(v.x), __float2half_rn(v.y),
                       __float2half_rn(v.z), __float2half_rn(v.w)};
        *(uint2*)(g_x + i) = *(uint2*)h;
        return;
    }
    const int j = id - 4096;
    const int n0 = (j % 96) * 32, c0 = (j / 96) * 32;
    const int tx = tid & 31, ty = tid >> 5;
#pragma unroll
    for (int jj = 0; jj < 4; jj++)
        ts[ty + jj * 8][tx] = wa[(size_t)(c0 + ty + jj * 8) * C3 + n0 + tx];
    __syncthreads();
#pragma unroll
    for (int jj = 0; jj < 4; jj++) {
        int n = n0 + ty + jj * 8;
        float v = ts[tx][ty + jj * 8];
        if (n < CC) v *= 0.18033688011112042f;  // (1/sqrt 64)*log2(e)
        g_wa[(size_t)n * CC + c0 + tx] = __float2half_rn(v);
    }
}

__global__ void __launch_bounds__(256) prep_wp(const float* __restrict__ wp) {
    __shared__ float ts[32][33];
    const int j = blockIdx.x;
    const int tid = threadIdx.x;
    const int n0 = (j % 32) * 32, c0 = (j / 32) * 32;
    const int tx = tid & 31, ty = tid >> 5;
#pragma unroll
    for (int jj = 0; jj < 4; jj++)
        ts[ty + jj * 8][tx] = wp[(size_t)(c0 + ty + jj * 8) * CC + n0 + tx];
    __syncthreads();
#pragma unroll
    for (int jj = 0; jj < 4; jj++) {
        int n = n0 + ty + jj * 8;
        g_wp[(size_t)n * CC + c0 + tx] = __float2half_rn(ts[tx][ty + jj * 8]);
    }
}

// ---------------- mma.sync GEMM (CTA 128x128, k-chunk 64, 3 stages, 2 CTA/SM) ----------------
// MODE 0: qkv = x * w_attn^T  -> g_q/g_k/g_v fp16   (per-half: M=2048, N=3072)
// MODE 1: out = y * w_proj^T  -> fp32 out           (per-half: M=2048, N=1024)
template<int MODE>
__global__ void __launch_bounds__(256, 2) gemm_mma(float* __restrict__ outp, int moff) {
    constexpr int NTILE = 128;
    constexpr int NC  = 16;           // k chunks of 64
    constexpr int LDA = CC, LDB = CC;
    constexpr int WN  = NTILE / 2;
    constexpr int NN8 = WN / 8;
    constexpr int NJ  = WN / 16;
    constexpr int RST = 144;          // 128B data + 16B pad per row
    constexpr int ASZ = 128 * RST;
    constexpr int STG = 2 * ASZ;
    constexpr int NSTG = 3;

    extern __shared__ char sm[];
    const uint32_t smu = smem_u32(sm);
    const int tid = threadIdx.x, lane = tid & 31, wid = tid >> 5;
    const int wm = wid & 3, wn = wid >> 2;
    const int warpM = wm * 32, warpN = wn * WN;
    const int nt = blockIdx.x, mt = blockIdx.y + moff;
    const int m0 = mt * 128, n0 = nt * NTILE;

    const __half *a_p, *b_p;
    if constexpr (MODE == 0) {
        a_p = g_x + (size_t)m0 * CC;
        b_p = g_wa + (size_t)n0 * CC;
    } else {
        a_p = g_y + (size_t)m0 * CC;
        b_p = g_wp + (size_t)n0 * CC;
    }

    auto load_stage = [&](int st, int kc) {
        const uint32_t s0 = smu + st * STG;
        const int k0 = kc * 64;
#pragma unroll
        for (int i0 = 0; i0 < 128 * 8; i0 += 256) {
            int i = i0 + tid, r = i >> 3, c = i & 7;
            uint32_t sa = s0 + r * RST + c * 16;
            cp16(sa,       (const char*)(a_p + (size_t)r * LDA + k0) + c * 16);
            cp16(sa + ASZ, (const char*)(b_p + (size_t)r * LDB + k0) + c * 16);
        }
        asm volatile("cp.async.commit_group;" ::: "memory");
    };

    const int grp = lane >> 3, r8 = lane & 7;
    const uint32_t aOff = (uint32_t)((warpM + r8 + (grp & 1) * 8) * RST + (grp >> 1) * 16);
    const uint32_t bOff = (uint32_t)((warpN + r8 + (grp >> 1) * 8) * RST + (grp & 1) * 16);

    float acc[2][NN8][4];
#pragma unroll
    for (int mi = 0; mi < 2; mi++)
#pragma unroll
        for (int ni = 0; ni < NN8; ni++)
#pragma unroll
            for (int e = 0; e < 4; e++) acc[mi][ni][e] = 0.f;

    load_stage(0, 0);
    load_stage(1, 1);

    int st = 0;
    for (int c = 0; c < NC; c++) {
        if (c + 2 < NC) { asm volatile("cp.async.wait_group 1;" ::: "memory"); }
        else            { asm volatile("cp.async.wait_group 0;" ::: "memory"); }
        __syncthreads();
        if (c + 2 < NC) {
            int st2 = st + 2; if (st2 >= NSTG) st2 -= NSTG;
            load_stage(st2, c + 2);
        }

        const uint32_t sA = smu + st * STG;
        const uint32_t sB = sA + ASZ;
#pragma unroll
        for (int pair = 0; pair < 2; pair++) {
            uint32_t aF[2][2][4], bF[2][NJ][4];
#pragma unroll
            for (int k2 = 0; k2 < 2; k2++) {
                const uint32_t kb = (pair * 2 + k2) * 32;
                ldm_x4(sA + aOff + kb,            aF[k2][0]);
                ldm_x4(sA + aOff + 16 * RST + kb, aF[k2][1]);
#pragma unroll
                for (int nj = 0; nj < NJ; nj++)
                    ldm_x4(sB + bOff + nj * 16 * RST + kb, bF[k2][nj]);
            }
#pragma unroll
            for (int k2 = 0; k2 < 2; k2++)
#pragma unroll
                for (int mi = 0; mi < 2; mi++)
#pragma unroll
                    for (int ni = 0; ni < NN8; ni++)
                        mma16816(acc[mi][ni], aF[k2][mi], &bF[k2][ni >> 1][(ni & 1) * 2]);
        }
        if (++st == NSTG) st = 0;
    }

    const int row_l = lane >> 2, col_l = (lane & 3) * 2;
#pragma unroll
    for (int mi = 0; mi < 2; mi++) {
#pragma unroll
        for (int ni = 0; ni < NN8; ni++) {
            const int gr0 = m0 + warpM + mi * 16 + row_l;
            const int gc  = n0 + warpN + ni * 8 + col_l;
            const float* cc = acc[mi][ni];
            if constexpr (MODE == 0) {
                __half* dst;
                int gcl;
                if (gc < CC)           { dst = g_q; gcl = gc; }
                else if (gc < 2 * CC)  { dst = g_k; gcl = gc - CC; }
                else                   { dst = g_v; gcl = gc - 2 * CC; }
                *(uint32_t*)(dst + (size_t)gr0 * CC + gcl)       = pack2h(cc[0], cc[1]);
                *(uint32_t*)(dst + (size_t)(gr0 + 8) * CC + gcl) = pack2h(cc[2], cc[3]);
            } else {
                *(float2*)(outp + (size_t)gr0 * CC + gc)       = make_float2(cc[0], cc[1]);
                *(float2*)(outp + (size_t)(gr0 + 8) * CC + gc) = make_float2(cc[2], cc[3]);
            }
        }
    }
}

// ---------------- fused flash attention: 4 warps x 32 q-rows, 3-stage pipeline ----------------
__global__ void __launch_bounds__(128) flash_k(int bhoff) {
    constexpr int RSTR = 144;
    constexpr int BUF  = 64 * RSTR;
    constexpr int STG  = 2 * BUF;
    constexpr int NSTG = 3;
    constexpr int NT   = TT / 64;

    extern __shared__ char sm[];
    const uint32_t smu = smem_u32(sm);
    const int tid = threadIdx.x, lane = tid & 31, wid = tid >> 5;
    const int qt = blockIdx.x, bh = blockIdx.y + bhoff;
    const int b = bh >> 4, h = bh & 15;
    const int r = lane >> 2, cq = (lane & 3) * 2;

    const size_t qbase = ((size_t)b * TT + qt * 128 + wid * 32) * CC + h * DD;
    uint32_t qf[2][4][4];
#pragma unroll
    for (int mb = 0; mb < 2; mb++)
#pragma unroll
        for (int kc = 0; kc < 4; kc++)
#pragma unroll
            for (int e = 0; e < 4; e++) {
                size_t off = qbase + (size_t)(mb * 16 + r + (e & 1) * 8) * CC
                           + kc * 16 + cq + (e >> 1) * 8;
                qf[mb][kc][e] = *(const uint32_t*)(g_q + off);
            }

    float oacc[2][8][4];
#pragma unroll
    for (int mb = 0; mb < 2; mb++)
#pragma unroll
        for (int nf = 0; nf < 8; nf++)
#pragma unroll
            for (int e = 0; e < 4; e++) oacc[mb][nf][e] = 0.f;
    float mrow[2][2] = {{-1e30f, -1e30f}, {-1e30f, -1e30f}};
    float lrow[2][2] = {{0.f, 0.f}, {0.f, 0.f}};

    const int grp = lane >> 3, r8 = lane & 7;
    const uint32_t kOff = (uint32_t)((r8 + (grp >> 1) * 8) * RSTR + (grp & 1) * 16);
    const uint32_t vOff = (uint32_t)(((grp & 1) * 8 + r8) * RSTR + (grp >> 1) * 16);
    const size_t kvb = (size_t)b * TT * CC + h * DD;

    auto load_tile = [&](int kt, int st) {
        const uint32_t s0 = smu + st * STG;
        const int t0 = kt * 64;
#pragma unroll
        for (int it = 0; it < 4; it++) {
            int i = it * 128 + tid;
            int rr = i >> 3, c = i & 7;
            uint32_t sa = s0 + rr * RSTR + c * 16;
            cp16(sa,       (const char*)(g_k + kvb + (size_t)(t0 + rr) * CC) + c * 16);
            cp16(sa + BUF, (const char*)(g_v + kvb + (size_t)(t0 + rr) * CC) + c * 16);
        }
        asm volatile("cp.async.commit_group;" ::: "memory");
    };

    load_tile(0, 0);
    load_tile(1, 1);

    int st = 0;
    for (int kt = 0; kt < NT; kt++) {
        if (kt + 2 < NT) { asm volatile("cp.async.wait_group 1;" ::: "memory"); }
        else             { asm volatile("cp.async.wait_group 0;" ::: "memory"); }
        __syncthreads();
        if (kt + 2 < NT) {
            int st2 = st + 2; if (st2 >= NSTG) st2 -= NSTG;
            load_tile(kt + 2, st2);
        }

        const uint32_t sK = smu + st * STG;
        const uint32_t sV = sK + BUF;

        float sacc[2][8][4];
#pragma unroll
        for (int mb = 0; mb < 2; mb++)
#pragma unroll
            for (int nf = 0; nf < 8; nf++)
#pragma unroll
                for (int e = 0; e < 4; e++) sacc[mb][nf][e] = 0.f;
#pragma unroll
        for (int kk = 0; kk < 4; kk++) {
            uint32_t bF[4][4];
#pragma unroll
            for (int nj = 0; nj < 4; nj++)
                ldm_x4(sK + kOff + nj * 16 * RSTR + kk * 32, bF[nj]);
#pragma unroll
            for (int mb = 0; mb < 2; mb++)
#pragma unroll
                for (int nf = 0; nf < 8; nf++)
                    mma16816(sacc[mb][nf], qf[mb][kk], &bF[nf >> 1][(nf & 1) * 2]);
        }

#pragma unroll
        for (int mb = 0; mb < 2; mb++) {
            float mx0 = -1e30f, mx1 = -1e30f;
#pragma unroll
            for (int nf = 0; nf < 8; nf++) {
                mx0 = fmaxf(mx0, fmaxf(sacc[mb][nf][0], sacc[mb][nf][1]));
                mx1 = fmaxf(mx1, fmaxf(sacc[mb][nf][2], sacc[mb][nf][3]));
            }
            mx0 = fmaxf(mx0, __shfl_xor_sync(0xffffffffu, mx0, 1));
            mx0 = fmaxf(mx0, __shfl_xor_sync(0xffffffffu, mx0, 2));
            mx1 = fmaxf(mx1, __shfl_xor_sync(0xffffffffu, mx1, 1));
            mx1 = fmaxf(mx1, __shfl_xor_sync(0xffffffffu, mx1, 2));
            const float mn0 = fmaxf(mrow[mb][0], mx0), mn1 = fmaxf(mrow[mb][1], mx1);
            const float al0 = ex2(mrow[mb][0] - mn0), al1 = ex2(mrow[mb][1] - mn1);
            float ls0 = 0.f, ls1 = 0.f;
#pragma unroll
            for (int nf = 0; nf < 8; nf++) {
                sacc[mb][nf][0] = ex2(sacc[mb][nf][0] - mn0);
                sacc[mb][nf][1] = ex2(sacc[mb][nf][1] - mn0);
                sacc[mb][nf][2] = ex2(sacc[mb][nf][2] - mn1);
                sacc[mb][nf][3] = ex2(sacc[mb][nf][3] - mn1);
                ls0 += sacc[mb][nf][0] + sacc[mb][nf][1];
                ls1 += sacc[mb][nf][2] + sacc[mb][nf][3];
            }
            ls0 += __shfl_xor_sync(0xffffffffu, ls0, 1);
            ls0 += __shfl_xor_sync(0xffffffffu, ls0, 2);
            ls1 += __shfl_xor_sync(0xffffffffu, ls1, 1);
            ls1 += __shfl_xor_sync(0xffffffffu, ls1, 2);
            lrow[mb][0] = lrow[mb][0] * al0 + ls0; mrow[mb][0] = mn0;
            lrow[mb][1] = lrow[mb][1] * al1 + ls1; mrow[mb][1] = mn1;
#pragma unroll
            for (int nf = 0; nf < 8; nf++) {
                oacc[mb][nf][0] *= al0; oacc[mb][nf][1] *= al0;
                oacc[mb][nf][2] *= al1; oacc[mb][nf][3] *= al1;
            }
        }

        uint32_t pf[2][4][4];
#pragma unroll
        for (int mb = 0; mb < 2; mb++)
#pragma unroll
            for (int kc = 0; kc < 4; kc++) {
                pf[mb][kc][0] = pack2h(sacc[mb][2 * kc][0],     sacc[mb][2 * kc][1]);
                pf[mb][kc][1] = pack2h(sacc[mb][2 * kc][2],     sacc[mb][2 * kc][3]);
                pf[mb][kc][2] = pack2h(sacc[mb][2 * kc + 1][0], sacc[mb][2 * kc + 1][1]);
                pf[mb][kc][3] = pack2h(sacc[mb][2 * kc + 1][2], sacc[mb][2 * kc + 1][3]);
            }

#pragma unroll
        for (int kc = 0; kc < 4; kc++) {
            uint32_t vF[4][4];
#pragma unroll
            for (int db = 0; db < 4; db++)
                ldm_x4t(sV + kc * 16 * RSTR + vOff + db * 32, vF[db]);
#pragma unroll
            for (int mb = 0; mb < 2; mb++)
#pragma unroll
                for (int nf = 0; nf < 8; nf++)
                    mma16816(oacc[mb][nf], pf[mb][kc], &vF[nf >> 1][(nf & 1) * 2]);
        }
        if (++st == NSTG) st = 0;
    }

#pragma unroll
    for (int mb = 0; mb < 2; mb++) {
        const float inv0 = 1.f / lrow[mb][0], inv1 = 1.f / lrow[mb][1];
        const size_t yb = ((size_t)b * TT + qt * 128 + wid * 32 + mb * 16) * CC + h * DD;
#pragma unroll
        for (int nf = 0; nf < 8; nf++) {
            const int col = nf * 8 + cq;
            *(uint32_t*)(g_y + yb + (size_t)r * CC + col) =
                pack2h(oacc[mb][nf][0] * inv0, oacc[mb][nf][1] * inv0);
            *(uint32_t*)(g_y + yb + (size_t)(r + 8) * CC + col) =
                pack2h(oacc[mb][nf][2] * inv1, oacc[mb][nf][3] * inv1);
        }
    }
}

// ---------------- host launcher: legal capture fork ----------------
extern "C" void kernel_launch(void* const* d_in, const int* in_sizes, int n_in,
                              void* d_out, int out_size) {
    const float* x  = (const float*)d_in[0];
    const float* wa = (const float*)d_in[1];
    const float* wp = (const float*)d_in[2];
    float* out = (float*)d_out;

    constexpr int SM_GEMM  = 3 * 2 * 128 * 144;  // 110592
    constexpr int SM_FLASH = 3 * 2 * 64 * 144;   // 55296

    static cudaStream_t s2 = nullptr;
    static cudaEvent_t e_fork = nullptr, e_join = nullptr, e_wp = nullptr, e_x = nullptr;
    if (!s2) {
        cudaStreamCreateWithFlags(&s2, cudaStreamNonBlocking);
        cudaEventCreateWithFlags(&e_fork, cudaEventDisableTiming);
        cudaEventCreateWithFlags(&e_join, cudaEventDisableTiming);
        cudaEventCreateWithFlags(&e_wp,   cudaEventDisableTiming);
        cudaEventCreateWithFlags(&e_x,    cudaEventDisableTiming);
        cudaFuncSetAttribute((const void*)gemm_mma<0>, cudaFuncAttributeMaxDynamicSharedMemorySize, SM_GEMM);
        cudaFuncSetAttribute((const void*)gemm_mma<1>, cudaFuncAttributeMaxDynamicSharedMemorySize, SM_GEMM);
        cudaFuncSetAttribute((const void*)flash_k,     cudaFuncAttributeMaxDynamicSharedMemorySize, SM_FLASH);
    }

    // fork s2 off the capture-origin stream FIRST (legal capture pattern)
    cudaEventRecord(e_fork, 0);
    cudaStreamWaitEvent(s2, e_fork, 0);

    // concurrent preps: w_proj on s2, x + w_attn on stream 0
    prep_wp<<<1024, 256, 0, s2>>>(wp);
    cudaEventRecord(e_wp, s2);
    prep_xwa<<<7168, 256>>>(x, wa);

    // batch-1 chain needs x/w_attn prep done
    cudaEventRecord(e_x, 0);
    cudaStreamWaitEvent(s2, e_x, 0);

    // batch 0 chain (default stream)
    gemm_mma<0><<<dim3(C3 / 128, 16), 256, SM_GEMM>>>(nullptr, 0);
    flash_k<<<dim3(TT / 128, 16), 128, SM_FLASH>>>(0);
    cudaStreamWaitEvent(0, e_wp, 0);   // proj needs w_proj prep (finished long ago)
    gemm_mma<1><<<dim3(CC / 128, 16), 256, SM_GEMM>>>(out, 0);

    // batch 1 chain (s2) — wp prep already ordered on this stream
    gemm_mma<0><<<dim3(C3 / 128, 16), 256, SM_GEMM, s2>>>(nullptr, 16);
    flash_k<<<dim3(TT / 128, 16), 128, SM_FLASH, s2>>>(16);
    gemm_mma<1><<<dim3(CC / 128, 16), 256, SM_GEMM, s2>>>(out, 16);

    cudaEventRecord(e_join, s2);
    cudaStreamWaitEvent(0, e_join, 0);
}